// round 12
// baseline (speedup 1.0000x reference)
#include <cuda_runtime.h>

// Sizes (fixed by the problem)
#define NB 8      // batch
#define CC 96     // channels
#define HH 32     // downsampled H=W
#define LL 1024   // HH*HH
#define M2 1536   // CC*16 rows of the paste GEMM

// ---------------- scratch (static device memory; no allocations) ----------
__device__ float g_bs  [NB*CC*LL];              // bs  [n][c][q]
__device__ float g_fs  [NB*CC*LL];              // fs  [n][c][p]
__device__ float g_E   [NB*LL];                 // per-pixel sum_c bs^2
__device__ float g_invn[NB*LL];                 // 1 / max(patch L2 norm, EPS)
__device__ float g_D   [NB*LL*LL];              // D = bs^T fs ; later reused as Z
__device__ float g_Y   [NB*LL*LL];              // yi ; yfused*SCALE ; softmax (in place)
__device__ float g_Bp  [(size_t)NB*LL*M2];      // patches, layout [n][q][m], m=c*16+di*4+ei
__device__ float g_T   [(size_t)NB*M2*LL];      // T[n][m][p]

// ---------------- gather stride-2 subsamples ------------------------------
__global__ void k_gather(const float* __restrict__ f, const float* __restrict__ b) {
    int i = blockIdx.x * 256 + threadIdx.x;            // over NB*CC*LL
    if (i >= NB*CC*LL) return;
    int q  = i & (LL-1);
    int nc = i >> 10;
    int hq = q >> 5, wq = q & 31;
    int src = (nc * 64 + 2*hq) * 64 + 2*wq;
    g_fs[i] = f[src];
    g_bs[i] = b[src];
}

// ---------------- E[n][q] = sum_c bs^2 ------------------------------------
__global__ void k_E() {
    int i = blockIdx.x * 256 + threadIdx.x;            // 8192
    if (i >= NB*LL) return;
    int n = i >> 10, q = i & (LL-1);
    const float* p = g_bs + n*CC*LL + q;
    float s = 0.f;
#pragma unroll 8
    for (int c = 0; c < CC; ++c) { float v = p[c*LL]; s += v*v; }
    g_E[i] = s;
}

// ---------------- invn[n][q] = 1/max(sqrt(3x3 sum of E), EPS) --------------
__global__ void k_invn() {
    int i = blockIdx.x * 256 + threadIdx.x;            // 8192
    if (i >= NB*LL) return;
    int n = i >> 10, q = i & (LL-1);
    int h = q >> 5, w = q & 31;
    float s = 0.f;
#pragma unroll
    for (int dh = -1; dh <= 1; ++dh)
#pragma unroll
        for (int dw = -1; dw <= 1; ++dw) {
            int hh = h + dh, ww = w + dw;
            if ((unsigned)hh < 32u && (unsigned)ww < 32u)
                s += g_E[n*LL + hh*32 + ww];
        }
    float nm = fmaxf(sqrtf(s), 1e-4f);
    g_invn[i] = 1.0f / nm;
}

// ---------------- SGEMM: C[M][N] = sum_k A[k][M] * B[k][N] ----------------
// SEL==0 : g_bs (96x1024)   * g_fs (96x1024)   -> g_D (1024x1024)
// SEL==1 : g_Bp (1024x1536) * g_Y  (1024x1024) -> g_T (1536x1024)
template<int M, int N, int K, int SEL>
__global__ __launch_bounds__(256, 2) void sgemm() {
    constexpr int BM = 128, BN = 128, BK = 8;
    const int n = blockIdx.z;
    const float* __restrict__ A = (SEL == 0 ? g_bs : g_Bp) + (size_t)n * M * K;
    const float* __restrict__ B = (SEL == 0 ? g_fs : g_Y ) + (size_t)n * N * K;
    float*       __restrict__ C = (SEL == 0 ? g_D  : g_T ) + (size_t)n * M * N;

    const int bm = blockIdx.y * BM;
    const int bn = blockIdx.x * BN;

    __shared__ __align__(16) float As[2][BK][BM];
    __shared__ __align__(16) float Bs[2][BK][BN];

    const int tid  = threadIdx.x;
    const int lrow = tid >> 5;                 // 0..7
    const int lcol = (tid & 31) << 2;          // 0..124
    const int tx   = tid & 15;
    const int ty   = tid >> 4;

    const float* Aload = A + (size_t)lrow * M + bm + lcol;
    const float* Bload = B + (size_t)lrow * N + bn + lcol;

    float acc[8][8];
#pragma unroll
    for (int i = 0; i < 8; ++i)
#pragma unroll
        for (int j = 0; j < 8; ++j) acc[i][j] = 0.f;

    float4 pa = *(const float4*)Aload;
    float4 pb = *(const float4*)Bload;
    int cur = 0;
    *(float4*)&As[0][lrow][lcol] = pa;
    *(float4*)&Bs[0][lrow][lcol] = pb;
    __syncthreads();

    const int NT = K / BK;
    for (int kt = 0; kt < NT; ++kt) {
        if (kt + 1 < NT) {
            pa = *(const float4*)(Aload + (size_t)(kt + 1) * BK * M);
            pb = *(const float4*)(Bload + (size_t)(kt + 1) * BK * N);
        }
#pragma unroll
        for (int kk = 0; kk < BK; ++kk) {
            float a[8], bf[8];
            *(float4*)&a [0] = *(const float4*)&As[cur][kk][ty*4];
            *(float4*)&a [4] = *(const float4*)&As[cur][kk][64 + ty*4];
            *(float4*)&bf[0] = *(const float4*)&Bs[cur][kk][tx*4];
            *(float4*)&bf[4] = *(const float4*)&Bs[cur][kk][64 + tx*4];
#pragma unroll
            for (int i = 0; i < 8; ++i)
#pragma unroll
                for (int j = 0; j < 8; ++j)
                    acc[i][j] += a[i] * bf[j];
        }
        if (kt + 1 < NT) {
            cur ^= 1;
            *(float4*)&As[cur][lrow][lcol] = pa;
            *(float4*)&Bs[cur][lrow][lcol] = pb;
            __syncthreads();
        }
    }

#pragma unroll
    for (int ih = 0; ih < 2; ++ih)
#pragma unroll
        for (int i2 = 0; i2 < 4; ++i2) {
            int r = bm + ih*64 + ty*4 + i2;
            float* cp = C + (size_t)r * N + bn;
            float4 v0 = make_float4(acc[ih*4+i2][0], acc[ih*4+i2][1],
                                    acc[ih*4+i2][2], acc[ih*4+i2][3]);
            float4 v1 = make_float4(acc[ih*4+i2][4], acc[ih*4+i2][5],
                                    acc[ih*4+i2][6], acc[ih*4+i2][7]);
            *(float4*)(cp + tx*4)      = v0;
            *(float4*)(cp + 64 + tx*4) = v1;
        }
}

// ---------------- yi = masked 3x3 diagonal combine of D, scaled by invn ---
__global__ void k_yi() {
    unsigned g = blockIdx.x * 256u + threadIdx.x;      // over NB * LL*LL
    int n = g >> 20;
    int e = g & (LL*LL - 1);
    int a  = e >> 10, bb = e & (LL-1);
    int hq = a >> 5, wq = a & 31, hp = bb >> 5, wp = bb & 31;
    const float* D = g_D + (size_t)n * LL * LL;
    float s = 0.f;
#pragma unroll
    for (int dh = -1; dh <= 1; ++dh)
#pragma unroll
        for (int dw = -1; dw <= 1; ++dw) {
            if ((unsigned)(hq+dh) < 32u && (unsigned)(wq+dw) < 32u &&
                (unsigned)(hp+dh) < 32u && (unsigned)(wp+dw) < 32u) {
                int off = dh*32 + dw;
                s += D[e + off*1025];
            }
        }
    g_Y[(size_t)n * LL * LL + e] = s * g_invn[n*LL + a];
}

// ---------------- fuse stage A: flat diagonal (zero-pad at ends of L) -----
__global__ void k_fuseA() {
    unsigned g = blockIdx.x * 256u + threadIdx.x;
    int n = g >> 20;
    int e = g & (LL*LL - 1);
    int a = e >> 10, bb = e & (LL-1);
    const float* Y = g_Y + (size_t)n * LL * LL;
    float s = 0.f;
#pragma unroll
    for (int d = -1; d <= 1; ++d)
        if ((unsigned)(a + d) < (unsigned)LL && (unsigned)(bb + d) < (unsigned)LL)
            s += Y[e + d*1025];
    g_D[(size_t)n * LL * LL + e] = s;                  // Z stored in g_D
}

// ---------------- fuse stage B: w-major flat diagonal, fold SCALE=10 ------
__global__ void k_fuseB() {
    unsigned g = blockIdx.x * 256u + threadIdx.x;
    int n = g >> 20;
    int e = g & (LL*LL - 1);
    int hq = (e >> 15) & 31, wq = (e >> 10) & 31;
    int hp = (e >> 5)  & 31, wp =  e        & 31;
    int ap = wq*32 + hq, bp = wp*32 + hp;
    const float* Z = g_D + (size_t)n * LL * LL;
    float s = 0.f;
#pragma unroll
    for (int d = -1; d <= 1; ++d) {
        int a2 = ap + d, b2 = bp + d;
        if ((unsigned)a2 < (unsigned)LL && (unsigned)b2 < (unsigned)LL) {
            int q2 = ((a2 & 31) << 5) | (a2 >> 5);
            int p2 = ((b2 & 31) << 5) | (b2 >> 5);
            s += Z[(q2 << 10) | p2];
        }
    }
    g_Y[(size_t)n * LL * LL + e] = s * 10.0f;          // logits = yfused * SCALE
}

// ---------------- softmax over q (rows) per column p, in place ------------
__global__ void k_softmax() {
    int n  = blockIdx.x >> 5;
    int p0 = (blockIdx.x & 31) * 32;
    int tx = threadIdx.x & 31;
    int ty = threadIdx.x >> 5;                         // 0..7
    float* Y = g_Y + (size_t)n * LL * LL + p0 + tx;
    __shared__ float red[8][32];

    float m = -1e30f;
    for (int q = ty; q < LL; q += 8) m = fmaxf(m, Y[q*LL]);
    red[ty][tx] = m; __syncthreads();
    if (ty == 0) { float mm = red[0][tx];
#pragma unroll
        for (int j = 1; j < 8; ++j) mm = fmaxf(mm, red[j][tx]);
        red[0][tx] = mm; }
    __syncthreads();
    m = red[0][tx];
    __syncthreads();

    float s = 0.f;
    for (int q = ty; q < LL; q += 8) { float v = expf(Y[q*LL] - m); Y[q*LL] = v; s += v; }
    red[ty][tx] = s; __syncthreads();
    if (ty == 0) { float ss = red[0][tx];
#pragma unroll
        for (int j = 1; j < 8; ++j) ss += red[j][tx];
        red[0][tx] = ss; }
    __syncthreads();
    float inv = 1.0f / red[0][tx];
    for (int q = ty; q < LL; q += 8) Y[q*LL] *= inv;
}

// ---------------- gather raw 4x4 patches: Bp[n][q][m] ----------------------
__global__ void k_bp(const float* __restrict__ b) {
    unsigned idx = blockIdx.x * 256u + threadIdx.x;    // over NB*LL*M2 = 12,582,912
    if (idx >= (unsigned)(NB*LL)*M2) return;
    int m = idx % M2;
    unsigned t = idx / M2;
    int q = t & (LL-1), n = t >> 10;
    int c  = m >> 4;
    int de = m & 15, di = de >> 2, ei = de & 3;
    int hq = q >> 5, wq = q & 31;
    int row = 2*hq + di - 1, col = 2*wq + ei - 1;
    float v = 0.f;
    if ((unsigned)row < 64u && (unsigned)col < 64u)
        v = b[((n*CC + c)*64 + row)*64 + col];
    g_Bp[(size_t)idx] = v;
}

// ---------------- epilogue: paste-overlap gather from T -------------------
__global__ void k_out(float* __restrict__ out) {
    int idx = blockIdx.x * 256 + threadIdx.x;          // over NB*CC*64*64
    if (idx >= NB*CC*4096) return;
    int x = idx & 63, y = (idx >> 6) & 63;
    int c = (idx >> 12) % CC, n = idx / (CC * 4096);

    int hs[2], ds[2], ws[2], es[2];
    if (y & 1) { hs[0] = (y-1) >> 1; ds[0] = 2; hs[1] = (y+1) >> 1; ds[1] = 0; }
    else       { hs[0] =  y    >> 1; ds[0] = 1; hs[1] = (y >> 1)-1; ds[1] = 3; }
    if (x & 1) { ws[0] = (x-1) >> 1; es[0] = 2; ws[1] = (x+1) >> 1; es[1] = 0; }
    else       { ws[0] =  x    >> 1; es[0] = 1; ws[1] = (x >> 1)-1; es[1] = 3; }

    const float* T = g_T + (size_t)n * M2 * LL;
    float s = 0.f;
#pragma unroll
    for (int a = 0; a < 2; ++a) {
        if ((unsigned)hs[a] >= 32u) continue;
#pragma unroll
        for (int bq = 0; bq < 2; ++bq) {
            if ((unsigned)ws[bq] >= 32u) continue;
            int m = c*16 + ds[a]*4 + es[bq];
            s += T[(size_t)m * LL + hs[a]*32 + ws[bq]];
        }
    }
    out[idx] = 0.25f * s;
}

// ---------------- launch ---------------------------------------------------
extern "C" void kernel_launch(void* const* d_in, const int* in_sizes, int n_in,
                              void* d_out, int out_size) {
    const float* f = (const float*)d_in[0];
    const float* b = (const float*)d_in[1];
    float* out = (float*)d_out;

    k_gather<<<(NB*CC*LL + 255)/256, 256>>>(f, b);
    k_E   <<<(NB*LL + 255)/256, 256>>>();
    k_invn<<<(NB*LL + 255)/256, 256>>>();

    // D = bs^T fs  (M=N=1024, K=96)
    sgemm<1024, 1024, 96, 0><<<dim3(8, 8, NB), 256>>>();

    const int EL = (NB * LL * LL) / 256;               // 32768 blocks
    k_yi   <<<EL, 256>>>();
    k_fuseA<<<EL, 256>>>();
    k_fuseB<<<EL, 256>>>();
    k_softmax<<<NB * 32, 256>>>();

    k_bp<<<((unsigned)(NB*LL)*M2 + 255)/256, 256>>>(b);

    // T = Bp * S  (M=1536, N=1024, K=1024)
    sgemm<1536, 1024, 1024, 1><<<dim3(8, 12, NB), 256>>>();

    k_out<<<(NB*CC*4096 + 255)/256, 256>>>(out);
}

// round 13
// speedup vs baseline: 1.0489x; 1.0489x over previous
#include <cuda_runtime.h>

// Sizes (fixed by the problem)
#define NB 8      // batch
#define CC 96     // channels
#define HH 32     // downsampled H=W
#define LL 1024   // HH*HH
#define M2 1536   // CC*16 rows of the paste GEMM

// ---------------- scratch (static device memory; no allocations) ----------
__device__ float g_bs  [NB*CC*LL];              // bs  [n][c][q]
__device__ float g_fs  [NB*CC*LL];              // fs  [n][c][p]
__device__ float g_E   [NB*LL];                 // per-pixel sum_c bs^2
__device__ float g_invn[NB*LL];                 // 1 / max(patch L2 norm, EPS)
__device__ float g_D   [NB*LL*LL];              // D = bs^T fs ; later reused as Z
__device__ float g_Y   [NB*LL*LL];              // yi ; yfused*SCALE ; softmax (in place)
__device__ float g_Bp  [(size_t)NB*LL*M2];      // patches, layout [n][q][m], m=c*16+di*4+ei
__device__ float g_T   [(size_t)NB*M2*LL];      // T[n][m][p]

// ---------------- packed f32x2 helpers (Blackwell FFMA2) ------------------
__device__ __forceinline__ unsigned long long pack2(float x) {
    unsigned long long r;
    asm("mov.b64 %0, {%1, %1};" : "=l"(r) : "f"(x));
    return r;
}
__device__ __forceinline__ void ffma2(unsigned long long& d,
                                      unsigned long long a,
                                      unsigned long long b) {
    asm("fma.rn.f32x2 %0, %1, %2, %0;" : "+l"(d) : "l"(a), "l"(b));
}

// ---------------- gather stride-2 subsamples ------------------------------
__global__ void k_gather(const float* __restrict__ f, const float* __restrict__ b) {
    int i = blockIdx.x * 256 + threadIdx.x;            // over NB*CC*LL
    if (i >= NB*CC*LL) return;
    int q  = i & (LL-1);
    int nc = i >> 10;
    int hq = q >> 5, wq = q & 31;
    int src = (nc * 64 + 2*hq) * 64 + 2*wq;
    g_fs[i] = f[src];
    g_bs[i] = b[src];
}

// ---------------- E[n][q] = sum_c bs^2 ------------------------------------
__global__ void k_E() {
    int i = blockIdx.x * 256 + threadIdx.x;            // 8192
    if (i >= NB*LL) return;
    int n = i >> 10, q = i & (LL-1);
    const float* p = g_bs + n*CC*LL + q;
    float s = 0.f;
#pragma unroll 8
    for (int c = 0; c < CC; ++c) { float v = p[c*LL]; s += v*v; }
    g_E[i] = s;
}

// ---------------- invn[n][q] = 1/max(sqrt(3x3 sum of E), EPS) --------------
__global__ void k_invn() {
    int i = blockIdx.x * 256 + threadIdx.x;            // 8192
    if (i >= NB*LL) return;
    int n = i >> 10, q = i & (LL-1);
    int h = q >> 5, w = q & 31;
    float s = 0.f;
#pragma unroll
    for (int dh = -1; dh <= 1; ++dh)
#pragma unroll
        for (int dw = -1; dw <= 1; ++dw) {
            int hh = h + dh, ww = w + dw;
            if ((unsigned)hh < 32u && (unsigned)ww < 32u)
                s += g_E[n*LL + hh*32 + ww];
        }
    float nm = fmaxf(sqrtf(s), 1e-4f);
    g_invn[i] = 1.0f / nm;
}

// ---------------- SGEMM: C[M][N] = sum_k A[k][M] * B[k][N] ----------------
// SEL==0 : g_bs (96x1024)   * g_fs (96x1024)   -> g_D (1024x1024)
// SEL==1 : g_Bp (1024x1536) * g_Y  (1024x1024) -> g_T (1536x1024)
// Inner product uses packed fma.rn.f32x2 (FFMA2) -> 128 FMA/cyc/SM ceiling.
template<int M, int N, int K, int SEL>
__global__ __launch_bounds__(256, 2) void sgemm() {
    constexpr int BM = 128, BN = 128, BK = 8;
    const int n = blockIdx.z;
    const float* __restrict__ A = (SEL == 0 ? g_bs : g_Bp) + (size_t)n * M * K;
    const float* __restrict__ B = (SEL == 0 ? g_fs : g_Y ) + (size_t)n * N * K;
    float*       __restrict__ C = (SEL == 0 ? g_D  : g_T ) + (size_t)n * M * N;

    const int bm = blockIdx.y * BM;
    const int bn = blockIdx.x * BN;

    __shared__ __align__(16) float As[2][BK][BM];
    __shared__ __align__(16) float Bs[2][BK][BN];

    const int tid  = threadIdx.x;
    const int lrow = tid >> 5;                 // 0..7
    const int lcol = (tid & 31) << 2;          // 0..124
    const int tx   = tid & 15;
    const int ty   = tid >> 4;

    const float* Aload = A + (size_t)lrow * M + bm + lcol;
    const float* Bload = B + (size_t)lrow * N + bn + lcol;

    // acc2[i][jp] : packed pair (c[i][2jp], c[i][2jp+1]) -- 32 u64 = 64 regs
    unsigned long long acc2[8][4];
#pragma unroll
    for (int i = 0; i < 8; ++i)
#pragma unroll
        for (int j = 0; j < 4; ++j) acc2[i][j] = 0ULL;

    float4 pa = *(const float4*)Aload;
    float4 pb = *(const float4*)Bload;
    int cur = 0;
    *(float4*)&As[0][lrow][lcol] = pa;
    *(float4*)&Bs[0][lrow][lcol] = pb;
    __syncthreads();

    const int NT = K / BK;
    for (int kt = 0; kt < NT; ++kt) {
        if (kt + 1 < NT) {
            pa = *(const float4*)(Aload + (size_t)(kt + 1) * BK * M);
            pb = *(const float4*)(Bload + (size_t)(kt + 1) * BK * N);
        }
#pragma unroll
        for (int kk = 0; kk < BK; ++kk) {
            float a[8];
            ulonglong2 b0 = *(const ulonglong2*)&Bs[cur][kk][tx*4];
            ulonglong2 b1 = *(const ulonglong2*)&Bs[cur][kk][64 + tx*4];
            *(float4*)&a[0] = *(const float4*)&As[cur][kk][ty*4];
            *(float4*)&a[4] = *(const float4*)&As[cur][kk][64 + ty*4];
#pragma unroll
            for (int i = 0; i < 8; ++i) {
                unsigned long long ai = pack2(a[i]);
                ffma2(acc2[i][0], ai, b0.x);
                ffma2(acc2[i][1], ai, b0.y);
                ffma2(acc2[i][2], ai, b1.x);
                ffma2(acc2[i][3], ai, b1.y);
            }
        }
        if (kt + 1 < NT) {
            cur ^= 1;
            *(float4*)&As[cur][lrow][lcol] = pa;
            *(float4*)&Bs[cur][lrow][lcol] = pb;
            __syncthreads();
        }
    }

#pragma unroll
    for (int ih = 0; ih < 2; ++ih)
#pragma unroll
        for (int i2 = 0; i2 < 4; ++i2) {
            int row = ih*4 + i2;
            int r = bm + ih*64 + ty*4 + i2;
            float* cp = C + (size_t)r * N + bn;
            *(ulonglong2*)(cp + tx*4)      = make_ulonglong2(acc2[row][0], acc2[row][1]);
            *(ulonglong2*)(cp + 64 + tx*4) = make_ulonglong2(acc2[row][2], acc2[row][3]);
        }
}

// ---------------- yi = masked 3x3 diagonal combine of D, scaled by invn ---
__global__ void k_yi() {
    unsigned g = blockIdx.x * 256u + threadIdx.x;      // over NB * LL*LL
    int n = g >> 20;
    int e = g & (LL*LL - 1);
    int a  = e >> 10, bb = e & (LL-1);
    int hq = a >> 5, wq = a & 31, hp = bb >> 5, wp = bb & 31;
    const float* D = g_D + (size_t)n * LL * LL;
    float s = 0.f;
#pragma unroll
    for (int dh = -1; dh <= 1; ++dh)
#pragma unroll
        for (int dw = -1; dw <= 1; ++dw) {
            if ((unsigned)(hq+dh) < 32u && (unsigned)(wq+dw) < 32u &&
                (unsigned)(hp+dh) < 32u && (unsigned)(wp+dw) < 32u) {
                int off = dh*32 + dw;
                s += D[e + off*1025];
            }
        }
    g_Y[(size_t)n * LL * LL + e] = s * g_invn[n*LL + a];
}

// ---------------- fuse stage A: flat diagonal (zero-pad at ends of L) -----
__global__ void k_fuseA() {
    unsigned g = blockIdx.x * 256u + threadIdx.x;
    int n = g >> 20;
    int e = g & (LL*LL - 1);
    int a = e >> 10, bb = e & (LL-1);
    const float* Y = g_Y + (size_t)n * LL * LL;
    float s = 0.f;
#pragma unroll
    for (int d = -1; d <= 1; ++d)
        if ((unsigned)(a + d) < (unsigned)LL && (unsigned)(bb + d) < (unsigned)LL)
            s += Y[e + d*1025];
    g_D[(size_t)n * LL * LL + e] = s;                  // Z stored in g_D
}

// ---------------- fuse stage B: w-major flat diagonal, fold SCALE=10 ------
__global__ void k_fuseB() {
    unsigned g = blockIdx.x * 256u + threadIdx.x;
    int n = g >> 20;
    int e = g & (LL*LL - 1);
    int hq = (e >> 15) & 31, wq = (e >> 10) & 31;
    int hp = (e >> 5)  & 31, wp =  e        & 31;
    int ap = wq*32 + hq, bp = wp*32 + hp;
    const float* Z = g_D + (size_t)n * LL * LL;
    float s = 0.f;
#pragma unroll
    for (int d = -1; d <= 1; ++d) {
        int a2 = ap + d, b2 = bp + d;
        if ((unsigned)a2 < (unsigned)LL && (unsigned)b2 < (unsigned)LL) {
            int q2 = ((a2 & 31) << 5) | (a2 >> 5);
            int p2 = ((b2 & 31) << 5) | (b2 >> 5);
            s += Z[(q2 << 10) | p2];
        }
    }
    g_Y[(size_t)n * LL * LL + e] = s * 10.0f;          // logits = yfused * SCALE
}

// ---------------- softmax over q (rows) per column p, in place ------------
__global__ void k_softmax() {
    int n  = blockIdx.x >> 5;
    int p0 = (blockIdx.x & 31) * 32;
    int tx = threadIdx.x & 31;
    int ty = threadIdx.x >> 5;                         // 0..7
    float* Y = g_Y + (size_t)n * LL * LL + p0 + tx;
    __shared__ float red[8][32];

    float m = -1e30f;
    for (int q = ty; q < LL; q += 8) m = fmaxf(m, Y[q*LL]);
    red[ty][tx] = m; __syncthreads();
    if (ty == 0) { float mm = red[0][tx];
#pragma unroll
        for (int j = 1; j < 8; ++j) mm = fmaxf(mm, red[j][tx]);
        red[0][tx] = mm; }
    __syncthreads();
    m = red[0][tx];
    __syncthreads();

    float s = 0.f;
    for (int q = ty; q < LL; q += 8) { float v = expf(Y[q*LL] - m); Y[q*LL] = v; s += v; }
    red[ty][tx] = s; __syncthreads();
    if (ty == 0) { float ss = red[0][tx];
#pragma unroll
        for (int j = 1; j < 8; ++j) ss += red[j][tx];
        red[0][tx] = ss; }
    __syncthreads();
    float inv = 1.0f / red[0][tx];
    for (int q = ty; q < LL; q += 8) Y[q*LL] *= inv;
}

// ---------------- gather raw 4x4 patches: Bp[n][q][m] ----------------------
__global__ void k_bp(const float* __restrict__ b) {
    unsigned idx = blockIdx.x * 256u + threadIdx.x;    // over NB*LL*M2 = 12,582,912
    if (idx >= (unsigned)(NB*LL)*M2) return;
    int m = idx % M2;
    unsigned t = idx / M2;
    int q = t & (LL-1), n = t >> 10;
    int c  = m >> 4;
    int de = m & 15, di = de >> 2, ei = de & 3;
    int hq = q >> 5, wq = q & 31;
    int row = 2*hq + di - 1, col = 2*wq + ei - 1;
    float v = 0.f;
    if ((unsigned)row < 64u && (unsigned)col < 64u)
        v = b[((n*CC + c)*64 + row)*64 + col];
    g_Bp[(size_t)idx] = v;
}

// ---------------- epilogue: paste-overlap gather from T -------------------
__global__ void k_out(float* __restrict__ out) {
    int idx = blockIdx.x * 256 + threadIdx.x;          // over NB*CC*64*64
    if (idx >= NB*CC*4096) return;
    int x = idx & 63, y = (idx >> 6) & 63;
    int c = (idx >> 12) % CC, n = idx / (CC * 4096);

    int hs[2], ds[2], ws[2], es[2];
    if (y & 1) { hs[0] = (y-1) >> 1; ds[0] = 2; hs[1] = (y+1) >> 1; ds[1] = 0; }
    else       { hs[0] =  y    >> 1; ds[0] = 1; hs[1] = (y >> 1)-1; ds[1] = 3; }
    if (x & 1) { ws[0] = (x-1) >> 1; es[0] = 2; ws[1] = (x+1) >> 1; es[1] = 0; }
    else       { ws[0] =  x    >> 1; es[0] = 1; ws[1] = (x >> 1)-1; es[1] = 3; }

    const float* T = g_T + (size_t)n * M2 * LL;
    float s = 0.f;
#pragma unroll
    for (int a = 0; a < 2; ++a) {
        if ((unsigned)hs[a] >= 32u) continue;
#pragma unroll
        for (int bq = 0; bq < 2; ++bq) {
            if ((unsigned)ws[bq] >= 32u) continue;
            int m = c*16 + ds[a]*4 + es[bq];
            s += T[(size_t)m * LL + hs[a]*32 + ws[bq]];
        }
    }
    out[idx] = 0.25f * s;
}

// ---------------- launch ---------------------------------------------------
extern "C" void kernel_launch(void* const* d_in, const int* in_sizes, int n_in,
                              void* d_out, int out_size) {
    const float* f = (const float*)d_in[0];
    const float* b = (const float*)d_in[1];
    float* out = (float*)d_out;

    k_gather<<<(NB*CC*LL + 255)/256, 256>>>(f, b);
    k_E   <<<(NB*LL + 255)/256, 256>>>();
    k_invn<<<(NB*LL + 255)/256, 256>>>();

    // D = bs^T fs  (M=N=1024, K=96)
    sgemm<1024, 1024, 96, 0><<<dim3(8, 8, NB), 256>>>();

    const int EL = (NB * LL * LL) / 256;               // 32768 blocks
    k_yi   <<<EL, 256>>>();
    k_fuseA<<<EL, 256>>>();
    k_fuseB<<<EL, 256>>>();
    k_softmax<<<NB * 32, 256>>>();

    k_bp<<<((unsigned)(NB*LL)*M2 + 255)/256, 256>>>(b);

    // T = Bp * S  (M=1536, N=1024, K=1024)
    sgemm<1536, 1024, 1024, 1><<<dim3(8, 12, NB), 256>>>();

    k_out<<<(NB*CC*4096 + 255)/256, 256>>>(out);
}

// round 16
// speedup vs baseline: 1.3905x; 1.3256x over previous
#include <cuda_runtime.h>
#include <cuda_bf16.h>
#include <cstdint>

// Sizes (fixed by the problem)
#define NB 8      // batch
#define CC 96     // channels
#define LL 1024   // 32*32
#define M2 1536   // CC*16 rows of the paste GEMM

// ---------------- scratch (static device memory; no allocations) ----------
__device__ float g_bs  [NB*CC*LL];
__device__ float g_fs  [NB*CC*LL];
__device__ float g_E   [NB*LL];
__device__ float g_invn[NB*LL];
__device__ float g_D   [NB*LL*LL];
__device__ float g_Y   [NB*LL*LL];
__device__ __nv_bfloat16 g_BpH[(size_t)NB*M2*LL];   // Bp hi, [n][m][q] K-major
__device__ __nv_bfloat16 g_BpL[(size_t)NB*M2*LL];   // Bp lo
__device__ __nv_bfloat16 g_SH [(size_t)NB*LL*LL];   // S hi, [n][p][q] K-major
__device__ __nv_bfloat16 g_SL [(size_t)NB*LL*LL];   // S lo
__device__ float g_T   [(size_t)NB*M2*LL];          // T[n][m][p]

// ---------------- PTX helpers (all plain-sm_103-legal) --------------------
__device__ __forceinline__ uint32_t smem_u32(const void* p) {
    uint32_t a;
    asm("{ .reg .u64 t; cvta.to.shared.u64 t, %1; cvt.u32.u64 %0, t; }" : "=r"(a) : "l"(p));
    return a;
}
__device__ __forceinline__ void cp16(uint32_t dst, const void* src) {
    asm volatile("cp.async.cg.shared.global [%0], [%1], 16;" :: "r"(dst), "l"(src));
}
__device__ __forceinline__ void ldm4(uint32_t* r, uint32_t addr) {
    asm volatile("ldmatrix.sync.aligned.m8n8.x4.shared.b16 {%0,%1,%2,%3}, [%4];"
                 : "=r"(r[0]), "=r"(r[1]), "=r"(r[2]), "=r"(r[3]) : "r"(addr));
}
__device__ __forceinline__ void mma_bf(float* d, const uint32_t* a, uint32_t b0, uint32_t b1) {
    asm volatile(
        "mma.sync.aligned.m16n8k16.row.col.f32.bf16.bf16.f32 "
        "{%0,%1,%2,%3}, {%4,%5,%6,%7}, {%8,%9}, {%0,%1,%2,%3};"
        : "+f"(d[0]), "+f"(d[1]), "+f"(d[2]), "+f"(d[3])
        : "r"(a[0]), "r"(a[1]), "r"(a[2]), "r"(a[3]), "r"(b0), "r"(b1));
}

// ---------------- gather stride-2 subsamples ------------------------------
__global__ void k_gather(const float* __restrict__ f, const float* __restrict__ b) {
    int i = blockIdx.x * 256 + threadIdx.x;
    if (i >= NB*CC*LL) return;
    int q  = i & (LL-1);
    int nc = i >> 10;
    int hq = q >> 5, wq = q & 31;
    int src = (nc * 64 + 2*hq) * 64 + 2*wq;
    g_fs[i] = f[src];
    g_bs[i] = b[src];
}

// ---------------- E[n][q] = sum_c bs^2 ------------------------------------
__global__ void k_E() {
    int i = blockIdx.x * 256 + threadIdx.x;
    if (i >= NB*LL) return;
    int n = i >> 10, q = i & (LL-1);
    const float* p = g_bs + n*CC*LL + q;
    float s = 0.f;
#pragma unroll 8
    for (int c = 0; c < CC; ++c) { float v = p[c*LL]; s += v*v; }
    g_E[i] = s;
}

// ---------------- invn = 1/max(sqrt(3x3 sum of E), EPS) --------------------
__global__ void k_invn() {
    int i = blockIdx.x * 256 + threadIdx.x;
    if (i >= NB*LL) return;
    int n = i >> 10, q = i & (LL-1);
    int h = q >> 5, w = q & 31;
    float s = 0.f;
#pragma unroll
    for (int dh = -1; dh <= 1; ++dh)
#pragma unroll
        for (int dw = -1; dw <= 1; ++dw) {
            int hh = h + dh, ww = w + dw;
            if ((unsigned)hh < 32u && (unsigned)ww < 32u)
                s += g_E[n*LL + hh*32 + ww];
        }
    g_invn[i] = 1.0f / fmaxf(sqrtf(s), 1e-4f);
}

// ---------------- GEMM1 (fp32): D = bs^T fs  (K=96) ------------------------
__global__ __launch_bounds__(256, 2) void sgemm1() {
    constexpr int M = 1024, N = 1024, K = 96, BK = 8;
    const int n = blockIdx.z;
    const float* __restrict__ A = g_bs + (size_t)n * CC * LL;
    const float* __restrict__ B = g_fs + (size_t)n * CC * LL;
    float*       __restrict__ C = g_D  + (size_t)n * LL * LL;

    const int bm = blockIdx.y * 128;
    const int bn = blockIdx.x * 128;

    __shared__ __align__(16) float As[2][BK][128];
    __shared__ __align__(16) float Bs[2][BK][128];

    const int tid  = threadIdx.x;
    const int lrow = tid >> 5;
    const int lcol = (tid & 31) << 2;
    const int tx   = tid & 15;
    const int ty   = tid >> 4;

    const float* Aload = A + (size_t)lrow * M + bm + lcol;
    const float* Bload = B + (size_t)lrow * N + bn + lcol;

    float acc[8][8];
#pragma unroll
    for (int i = 0; i < 8; ++i)
#pragma unroll
        for (int j = 0; j < 8; ++j) acc[i][j] = 0.f;

    float4 pa = *(const float4*)Aload;
    float4 pb = *(const float4*)Bload;
    int cur = 0;
    *(float4*)&As[0][lrow][lcol] = pa;
    *(float4*)&Bs[0][lrow][lcol] = pb;
    __syncthreads();

    const int NT = K / BK;
    for (int kt = 0; kt < NT; ++kt) {
        if (kt + 1 < NT) {
            pa = *(const float4*)(Aload + (size_t)(kt + 1) * BK * M);
            pb = *(const float4*)(Bload + (size_t)(kt + 1) * BK * N);
        }
#pragma unroll
        for (int kk = 0; kk < BK; ++kk) {
            float a[8], bf[8];
            *(float4*)&a [0] = *(const float4*)&As[cur][kk][ty*4];
            *(float4*)&a [4] = *(const float4*)&As[cur][kk][64 + ty*4];
            *(float4*)&bf[0] = *(const float4*)&Bs[cur][kk][tx*4];
            *(float4*)&bf[4] = *(const float4*)&Bs[cur][kk][64 + tx*4];
#pragma unroll
            for (int i = 0; i < 8; ++i)
#pragma unroll
                for (int j = 0; j < 8; ++j)
                    acc[i][j] += a[i] * bf[j];
        }
        if (kt + 1 < NT) {
            cur ^= 1;
            *(float4*)&As[cur][lrow][lcol] = pa;
            *(float4*)&Bs[cur][lrow][lcol] = pb;
            __syncthreads();
        }
    }
#pragma unroll
    for (int ih = 0; ih < 2; ++ih)
#pragma unroll
        for (int i2 = 0; i2 < 4; ++i2) {
            int r = bm + ih*64 + ty*4 + i2;
            float* cp = C + (size_t)r * N + bn;
            *(float4*)(cp + tx*4)      = *(float4*)&acc[ih*4+i2][0];
            *(float4*)(cp + 64 + tx*4) = *(float4*)&acc[ih*4+i2][4];
        }
}

// ---------------- yi = masked 3x3 diagonal combine of D, scaled by invn ---
__global__ void k_yi() {
    unsigned g = blockIdx.x * 256u + threadIdx.x;
    int n = g >> 20;
    int e = g & (LL*LL - 1);
    int a  = e >> 10, bb = e & (LL-1);
    int hq = a >> 5, wq = a & 31, hp = bb >> 5, wp = bb & 31;
    const float* D = g_D + (size_t)n * LL * LL;
    float s = 0.f;
#pragma unroll
    for (int dh = -1; dh <= 1; ++dh)
#pragma unroll
        for (int dw = -1; dw <= 1; ++dw) {
            if ((unsigned)(hq+dh) < 32u && (unsigned)(wq+dw) < 32u &&
                (unsigned)(hp+dh) < 32u && (unsigned)(wp+dw) < 32u)
                s += D[e + (dh*32 + dw)*1025];
        }
    g_Y[(size_t)n * LL * LL + e] = s * g_invn[n*LL + a];
}

// ---------------- fuse stage A -------------------------------------------
__global__ void k_fuseA() {
    unsigned g = blockIdx.x * 256u + threadIdx.x;
    int n = g >> 20;
    int e = g & (LL*LL - 1);
    int a = e >> 10, bb = e & (LL-1);
    const float* Y = g_Y + (size_t)n * LL * LL;
    float s = 0.f;
#pragma unroll
    for (int d = -1; d <= 1; ++d)
        if ((unsigned)(a + d) < (unsigned)LL && (unsigned)(bb + d) < (unsigned)LL)
            s += Y[e + d*1025];
    g_D[(size_t)n * LL * LL + e] = s;
}

// ---------------- fuse stage B (w-major), fold SCALE=10 -------------------
__global__ void k_fuseB() {
    unsigned g = blockIdx.x * 256u + threadIdx.x;
    int n = g >> 20;
    int e = g & (LL*LL - 1);
    int hq = (e >> 15) & 31, wq = (e >> 10) & 31;
    int hp = (e >> 5)  & 31, wp =  e        & 31;
    int ap = wq*32 + hq, bp = wp*32 + hp;
    const float* Z = g_D + (size_t)n * LL * LL;
    float s = 0.f;
#pragma unroll
    for (int d = -1; d <= 1; ++d) {
        int a2 = ap + d, b2 = bp + d;
        if ((unsigned)a2 < (unsigned)LL && (unsigned)b2 < (unsigned)LL) {
            int q2 = ((a2 & 31) << 5) | (a2 >> 5);
            int p2 = ((b2 & 31) << 5) | (b2 >> 5);
            s += Z[(q2 << 10) | p2];
        }
    }
    g_Y[(size_t)n * LL * LL + e] = s * 10.0f;
}

// ---------------- softmax over q (rows) per column p, in place ------------
__global__ void k_softmax() {
    int n  = blockIdx.x >> 5;
    int p0 = (blockIdx.x & 31) * 32;
    int tx = threadIdx.x & 31;
    int ty = threadIdx.x >> 5;
    float* Y = g_Y + (size_t)n * LL * LL + p0 + tx;
    __shared__ float red[8][32];

    float m = -1e30f;
    for (int q = ty; q < LL; q += 8) m = fmaxf(m, Y[q*LL]);
    red[ty][tx] = m; __syncthreads();
    if (ty == 0) { float mm = red[0][tx];
#pragma unroll
        for (int j = 1; j < 8; ++j) mm = fmaxf(mm, red[j][tx]);
        red[0][tx] = mm; }
    __syncthreads();
    m = red[0][tx];
    __syncthreads();

    float s = 0.f;
    for (int q = ty; q < LL; q += 8) { float v = expf(Y[q*LL] - m); Y[q*LL] = v; s += v; }
    red[ty][tx] = s; __syncthreads();
    if (ty == 0) { float ss = red[0][tx];
#pragma unroll
        for (int j = 1; j < 8; ++j) ss += red[j][tx];
        red[0][tx] = ss; }
    __syncthreads();
    float inv = 1.0f / red[0][tx];
    for (int q = ty; q < LL; q += 8) Y[q*LL] *= inv;
}

// ---------------- transpose + bf16 hi/lo split of S -----------------------
// Y[q][p] (float) -> SH/SL[p][q] (bf16)
__global__ void k_split() {
    __shared__ float t[32][33];
    int n  = blockIdx.z;
    int p0 = blockIdx.x * 32, q0 = blockIdx.y * 32;
    int tx = threadIdx.x, ty = threadIdx.y;          // 32 x 8
    const float* Y = g_Y + (size_t)n * LL * LL;
#pragma unroll
    for (int j = 0; j < 32; j += 8)
        t[ty + j][tx] = Y[(size_t)(q0 + ty + j) * LL + p0 + tx];
    __syncthreads();
    __nv_bfloat16* SH = g_SH + (size_t)n * LL * LL;
    __nv_bfloat16* SL = g_SL + (size_t)n * LL * LL;
#pragma unroll
    for (int j = 0; j < 32; j += 8) {
        float v = t[tx][ty + j];
        __nv_bfloat16 h = __float2bfloat16(v);
        float r = v - __bfloat162float(h);
        size_t o = (size_t)(p0 + ty + j) * LL + q0 + tx;
        SH[o] = h;
        SL[o] = __float2bfloat16(r);
    }
}

// ---------------- raw 4x4 patches, K-major bf16 hi/lo ----------------------
__global__ void k_bp2(const float* __restrict__ b) {
    unsigned idx = blockIdx.x * 256u + threadIdx.x;   // over NB*M2*LL
    if (idx >= (unsigned)NB*M2*LL) return;
    int q = idx & (LL-1);
    unsigned t = idx >> 10;
    int m = t % M2, n = t / M2;
    int c  = m >> 4;
    int di = (m >> 2) & 3, ei = m & 3;
    int hq = q >> 5, wq = q & 31;
    int row = 2*hq + di - 1, col = 2*wq + ei - 1;
    float v = 0.f;
    if ((unsigned)row < 64u && (unsigned)col < 64u)
        v = b[((n*CC + c)*64 + row)*64 + col];
    __nv_bfloat16 h = __float2bfloat16(v);
    g_BpH[(size_t)idx] = h;
    g_BpL[(size_t)idx] = __float2bfloat16(v - __bfloat162float(h));
}

// ---------------- GEMM2 via mma.sync bf16 (3-MMA hi/lo split) -------------
// T[m][p] = sum_q Bp[m][q] * S[p][q]; CTA tile 128x128, warp tile 32x64,
// K staged 64 wide, cp.async double-buffered, XOR-swizzled ldmatrix.
#define TILE_B 16384
#define STAGE_B (4*TILE_B)
#define SMEM2  (2*STAGE_B)

__global__ __launch_bounds__(256, 1) void gemm2_mma() {
    extern __shared__ __align__(128) char smem[];
    const uint32_t sb = smem_u32(smem);
    const int tid  = threadIdx.x;
    const int lane = tid & 31, wid = tid >> 5;
    const int wm = wid & 3, wn = wid >> 2;           // 4 x 2 warp grid
    const int nb = blockIdx.z;
    const int bm = blockIdx.y * 128;
    const int bn = blockIdx.x * 128;

    const __nv_bfloat16* Ah = g_BpH + ((size_t)nb*M2 + bm)*LL;
    const __nv_bfloat16* Al = g_BpL + ((size_t)nb*M2 + bm)*LL;
    const __nv_bfloat16* Bh = g_SH  + ((size_t)nb*LL + bn)*LL;
    const __nv_bfloat16* Bl = g_SL  + ((size_t)nb*LL + bn)*LL;

    float acc[2][8][4];
#pragma unroll
    for (int mi = 0; mi < 2; ++mi)
#pragma unroll
        for (int nj = 0; nj < 8; ++nj)
#pragma unroll
            for (int v = 0; v < 4; ++v) acc[mi][nj][v] = 0.f;

    // loader: thread t copies 4 granules of 16B per tile, XOR-swizzled
    auto load_stage = [&](int s, int k0) {
        uint32_t base = sb + s*STAGE_B;
#pragma unroll
        for (int i = 0; i < 4; ++i) {
            int gid = tid*4 + i;                      // 0..1023
            int row = gid >> 3, g = gid & 7;
            uint32_t doff = row*128 + ((g ^ (row & 7)) << 4);
            size_t   soff = (size_t)row*LL + k0 + g*8;
            cp16(base +            doff, Ah + soff);
            cp16(base +   TILE_B + doff, Al + soff);
            cp16(base + 2*TILE_B + doff, Bh + soff);
            cp16(base + 3*TILE_B + doff, Bl + soff);
        }
        asm volatile("cp.async.commit_group;" ::: "memory");
    };

    load_stage(0, 0);
    for (int kt = 0; kt < 16; ++kt) {
        if (kt < 15) {
            load_stage((kt + 1) & 1, (kt + 1) * 64);
            asm volatile("cp.async.wait_group 1;" ::: "memory");
        } else {
            asm volatile("cp.async.wait_group 0;" ::: "memory");
        }
        __syncthreads();

        uint32_t base = sb + (kt & 1)*STAGE_B;
#pragma unroll
        for (int ks = 0; ks < 4; ++ks) {
            uint32_t ah[2][4], al[2][4], bh[4][4], bl[4][4];
            const int gsel = 2*ks + (lane >> 4);
#pragma unroll
            for (int mi = 0; mi < 2; ++mi) {
                int r = wm*32 + mi*16 + (lane & 15);
                uint32_t off = r*128 + ((gsel ^ (r & 7)) << 4);
                ldm4(ah[mi], base + off);
                ldm4(al[mi], base + TILE_B + off);
            }
#pragma unroll
            for (int bj = 0; bj < 4; ++bj) {
                int r = wn*64 + bj*16 + (lane & 15);
                uint32_t off = r*128 + ((gsel ^ (r & 7)) << 4);
                ldm4(bh[bj], base + 2*TILE_B + off);
                ldm4(bl[bj], base + 3*TILE_B + off);
            }
#pragma unroll
            for (int mi = 0; mi < 2; ++mi)
#pragma unroll
                for (int nj = 0; nj < 8; ++nj) {
                    const int bj = nj >> 1, o = nj & 1;
                    mma_bf(acc[mi][nj], ah[mi], bh[bj][o], bh[bj][2+o]);
                    mma_bf(acc[mi][nj], ah[mi], bl[bj][o], bl[bj][2+o]);
                    mma_bf(acc[mi][nj], al[mi], bh[bj][o], bh[bj][2+o]);
                }
        }
        __syncthreads();
    }

    // epilogue: C fragment -> g_T
    float* Tn = g_T + (size_t)nb*M2*LL;
    const int lr = lane >> 2, lc = (lane & 3) * 2;
#pragma unroll
    for (int mi = 0; mi < 2; ++mi)
#pragma unroll
        for (int nj = 0; nj < 8; ++nj) {
            int rb = bm + wm*32 + mi*16;
            int cb = bn + wn*64 + nj*8 + lc;
            *(float2*)(Tn + (size_t)(rb + lr    )*LL + cb) =
                make_float2(acc[mi][nj][0], acc[mi][nj][1]);
            *(float2*)(Tn + (size_t)(rb + lr + 8)*LL + cb) =
                make_float2(acc[mi][nj][2], acc[mi][nj][3]);
        }
}

// ---------------- epilogue: paste-overlap gather from T -------------------
__global__ void k_out(float* __restrict__ out) {
    int idx = blockIdx.x * 256 + threadIdx.x;
    if (idx >= NB*CC*4096) return;
    int x = idx & 63, y = (idx >> 6) & 63;
    int c = (idx >> 12) % CC, n = idx / (CC * 4096);

    int hs[2], ds[2], ws[2], es[2];
    if (y & 1) { hs[0] = (y-1) >> 1; ds[0] = 2; hs[1] = (y+1) >> 1; ds[1] = 0; }
    else       { hs[0] =  y    >> 1; ds[0] = 1; hs[1] = (y >> 1)-1; ds[1] = 3; }
    if (x & 1) { ws[0] = (x-1) >> 1; es[0] = 2; ws[1] = (x+1) >> 1; es[1] = 0; }
    else       { ws[0] =  x    >> 1; es[0] = 1; ws[1] = (x >> 1)-1; es[1] = 3; }

    const float* T = g_T + (size_t)n * M2 * LL;
    float s = 0.f;
#pragma unroll
    for (int a = 0; a < 2; ++a) {
        if ((unsigned)hs[a] >= 32u) continue;
#pragma unroll
        for (int bq = 0; bq < 2; ++bq) {
            if ((unsigned)ws[bq] >= 32u) continue;
            int m = c*16 + ds[a]*4 + es[bq];
            s += T[(size_t)m * LL + hs[a]*32 + ws[bq]];
        }
    }
    out[idx] = 0.25f * s;
}

// ---------------- launch ---------------------------------------------------
extern "C" void kernel_launch(void* const* d_in, const int* in_sizes, int n_in,
                              void* d_out, int out_size) {
    const float* f = (const float*)d_in[0];
    const float* b = (const float*)d_in[1];
    float* out = (float*)d_out;

    cudaFuncSetAttribute(gemm2_mma, cudaFuncAttributeMaxDynamicSharedMemorySize, SMEM2);

    k_gather<<<(NB*CC*LL + 255)/256, 256>>>(f, b);
    k_E   <<<(NB*LL + 255)/256, 256>>>();
    k_invn<<<(NB*LL + 255)/256, 256>>>();

    sgemm1<<<dim3(8, 8, NB), 256>>>();

    const int EL = (NB * LL * LL) / 256;
    k_yi   <<<EL, 256>>>();
    k_fuseA<<<EL, 256>>>();
    k_fuseB<<<EL, 256>>>();
    k_softmax<<<NB * 32, 256>>>();

    k_split<<<dim3(32, 32, NB), dim3(32, 8)>>>();
    k_bp2<<<((unsigned)NB*M2*LL + 255)/256, 256>>>(b);

    gemm2_mma<<<dim3(8, 12, NB), 256, SMEM2>>>();

    k_out<<<(NB*CC*4096 + 255)/256, 256>>>(out);
}